// round 6
// baseline (speedup 1.0000x reference)
#include <cuda_runtime.h>
#include <cuda_bf16.h>
#include <math.h>
#include <stdint.h>

// Problem dims (fixed)
#define Bv 32
#define Sv 1024
#define Dv 1024
#define Av 256
#define Ev 16
#define Mrows (Bv * Sv)   // 32768

// ---------------------------------------------------------------------------
// Persistent scratch (no cudaMalloc allowed)
// ---------------------------------------------------------------------------
__device__ float g_pre[(size_t)Mrows * Dv];            // pre-LN fp32
__device__ __nv_bfloat16 g_xh[(size_t)Mrows * Dv];     // hidden split hi
__device__ __nv_bfloat16 g_xl[(size_t)Mrows * Dv];     // hidden split lo
__device__ __nv_bfloat16 g_h1h[(size_t)Mrows * Av];    // stage1 out hi
__device__ __nv_bfloat16 g_h1l[(size_t)Mrows * Av];    // stage1 out lo
__device__ __nv_bfloat16 g_h2h[(size_t)Mrows * Av];    // stage2 out hi
__device__ __nv_bfloat16 g_h2l[(size_t)Mrows * Av];    // stage2 out lo
__device__ __nv_bfloat16 g_dwh[Av * Dv], g_dwl[Av * Dv];            // down_W
__device__ __nv_bfloat16 g_uwh[Dv * Av], g_uwl[Dv * Av];            // up_W
__device__ __nv_bfloat16 g_ewh[Ev * Av * Av], g_ewl[Ev * Av * Av];  // expert_W
__device__ int g_idx[Bv];
__device__ int g_valid[Bv];

// ---------------------------------------------------------------------------
__device__ __forceinline__ uint32_t smem_u32(const void* p) {
    uint32_t a;
    asm("{ .reg .u64 t; cvta.to.shared.u64 t, %1; cvt.u32.u64 %0, t; }" : "=r"(a) : "l"(p));
    return a;
}
#define LDSM4(r, addr) \
    asm volatile("ldmatrix.sync.aligned.m8n8.x4.shared.b16 {%0,%1,%2,%3}, [%4];" \
        : "=r"((r)[0]), "=r"((r)[1]), "=r"((r)[2]), "=r"((r)[3]) : "r"(addr))
#define MMA_OP(d, a, b0, b1) \
    asm volatile("mma.sync.aligned.m16n8k16.row.col.f32.bf16.bf16.f32 " \
        "{%0,%1,%2,%3}, {%4,%5,%6,%7}, {%8,%9}, {%0,%1,%2,%3};" \
        : "+f"((d)[0]), "+f"((d)[1]), "+f"((d)[2]), "+f"((d)[3]) \
        : "r"((a)[0]), "r"((a)[1]), "r"((a)[2]), "r"((a)[3]), "r"(b0), "r"(b1))
#define CP16(dst, src) \
    asm volatile("cp.async.cg.shared.global [%0], [%1], 16;" :: "r"(dst), "l"(src))
#define CPCOMMIT() asm volatile("cp.async.commit_group;" ::: "memory")
#define CPWAIT0()  asm volatile("cp.async.wait_group 0;" ::: "memory")

// ---------------------------------------------------------------------------
// domain_id may arrive as int32 or int64. Detect and normalize.
// ---------------------------------------------------------------------------
__global__ void prep_ids(const int* __restrict__ p) {
    bool is64 = true;
    for (int k = 0; k < 16; k++) {
        int hi = p[2 * k + 1];
        if (hi != 0 && hi != -1) { is64 = false; break; }
    }
    for (int b = 0; b < Bv; b++) {
        long long v;
        if (is64) {
            unsigned int lo = (unsigned int)p[2 * b];
            int hi = p[2 * b + 1];
            v = ((long long)hi << 32) | (long long)lo;
        } else {
            v = p[b];
        }
        g_valid[b] = (v >= 0 && v < Ev) ? 1 : 0;
        long long c = v < 0 ? 0 : (v > (Ev - 1) ? (Ev - 1) : v);
        g_idx[b] = (int)c;
    }
}

// Split fp32 array into bf16 hi/lo arrays (vectorized float4)
__global__ void split_w(const float* __restrict__ src,
                        __nv_bfloat16* __restrict__ H,
                        __nv_bfloat16* __restrict__ L, int n4) {
    for (int i = blockIdx.x * blockDim.x + threadIdx.x; i < n4;
         i += gridDim.x * blockDim.x) {
        float4 v = ((const float4*)src)[i];
        __nv_bfloat162 h0 = __floats2bfloat162_rn(v.x, v.y);
        __nv_bfloat162 h1 = __floats2bfloat162_rn(v.z, v.w);
        float2 f0 = __bfloat1622float2(h0);
        float2 f1 = __bfloat1622float2(h1);
        __nv_bfloat162 l0 = __floats2bfloat162_rn(v.x - f0.x, v.y - f0.y);
        __nv_bfloat162 l1 = __floats2bfloat162_rn(v.z - f1.x, v.w - f1.y);
        ((uint2*)H)[i] = make_uint2(*(uint32_t*)&h0, *(uint32_t*)&h1);
        ((uint2*)L)[i] = make_uint2(*(uint32_t*)&l0, *(uint32_t*)&l1);
    }
}

__device__ __forceinline__ float gelu_exact(float v) {
    return 0.5f * v * (1.0f + erff(v * 0.70710678118654752440f));
}

// Epilogue split-write of a float2 into hi/lo bf16 arrays.
__device__ __forceinline__ void ep_split(__nv_bfloat16* H, __nv_bfloat16* L,
                                         size_t off, float x, float y) {
    __nv_bfloat162 h = __floats2bfloat162_rn(x, y);
    float2 hf = __bfloat1622float2(h);
    __nv_bfloat162 l = __floats2bfloat162_rn(x - hf.x, y - hf.y);
    *(uint32_t*)(H + off) = *(uint32_t*)&h;
    *(uint32_t*)(L + off) = *(uint32_t*)&l;
}

// cp.async loader: ROWS x 64 bf16 chunk (hi+lo) into swizzled SMEM.
// 256 threads; ROWS/32 lines of 16B per half per thread.
template <int ROWS>
__device__ __forceinline__ void load_presplit(uint32_t dstHi, uint32_t dstLo,
                                              const __nv_bfloat16* __restrict__ hi,
                                              const __nv_bfloat16* __restrict__ lo,
                                              int tid, int K, int k0) {
#pragma unroll
    for (int i = 0; i < ROWS / 32; i++) {
        const int idx = tid + i * 256;
        const int row = idx >> 3;
        const int c8 = idx & 7;
        const uint32_t off = (uint32_t)(row * 128) +
                             (uint32_t)((c8 * 16) ^ ((row & 7) << 4));
        const size_t g = (size_t)row * K + k0 + c8 * 8;
        CP16(dstHi + off, hi + g);
        CP16(dstLo + off, lo + g);
    }
}

// ---------------------------------------------------------------------------
// bf16-split NT GEMM via mma.sync: C[128,256] block = A[M,K] * B[N,K]^T
// 3 MMA passes (hi*hi + hi*lo + lo*hi), fp32 accum.
// 256 threads, 8 warps as 2(M) x 4(N); warp tile 64x64 (mt=4 x nt=8).
// Per k16 step: 16 LDSM.x4 -> 96 MMAs (ratio 6). BK=64, 2-stage cp.async.
// SMEM stage: Ah(16K) Al(16K) Bh(32K) Bl(32K) = 96KB; 2 stages = 192KB.
// MODE 1: A = g_x presplit, B = down_W presplit; GELU -> g_h1h/l
// MODE 2: A = g_h1 presplit, B = expert_W[e] presplit; +bias/pass+emb -> g_h2h/l
// MODE 3: A = g_h2 presplit, B = up_W presplit; +bias+residual -> g_pre fp32
// ---------------------------------------------------------------------------
#define A_OFF 0u
#define AL_OFF 16384u
#define BH_OFF 32768u
#define BL_OFF 65536u
#define STAGE_B 98304u
#define SMEM_BYTES (2u * STAGE_B)

template <int MODE>
__global__ __launch_bounds__(256, 1)
void hmma_gemm(const float* __restrict__ bias,
               const float* __restrict__ extra) {
    constexpr int K  = (MODE == 1) ? Dv : Av;
    constexpr int N  = (MODE == 3) ? Dv : Av;
    constexpr int NC = K / 64;

    extern __shared__ char sm[];
    const uint32_t sbase = smem_u32(sm);

    const int tid  = threadIdx.x;
    const int lane = tid & 31;
    const int wid  = tid >> 5;
    const int wm   = wid & 1;     // warp row: 2 x 64 = 128 M
    const int wn   = wid >> 1;    // warp col: 4 x 64 = 256 N

    int m0;
    const int n0 = blockIdx.x * 256;
    const __nv_bfloat16 *Ah, *Al, *Bh, *Bl;
    const float* biasp = bias;
    const float* embp = nullptr;
    int valid = 1;
    if (MODE == 1) {
        m0 = blockIdx.y * 128;
        Ah = g_xh; Al = g_xl;
        Bh = g_dwh; Bl = g_dwl;
    } else if (MODE == 2) {
        const int b = blockIdx.z;
        const int e = g_idx[b];
        valid = g_valid[b];
        m0 = b * Sv + blockIdx.y * 128;
        Ah = g_h1h; Al = g_h1l;
        Bh = g_ewh + (size_t)e * Av * Av;
        Bl = g_ewl + (size_t)e * Av * Av;
        biasp = bias + (size_t)e * Av;
        embp = extra + (size_t)e * Av;
    } else {
        m0 = blockIdx.y * 128;
        Ah = g_h2h; Al = g_h2l;
        Bh = g_uwh; Bl = g_uwl;
    }

    const __nv_bfloat16* ArowH = Ah + (size_t)m0 * K;
    const __nv_bfloat16* ArowL = Al + (size_t)m0 * K;
    const __nv_bfloat16* BrowH = Bh + (size_t)n0 * K;
    const __nv_bfloat16* BrowL = Bl + (size_t)n0 * K;

    // Prologue: issue chunk 0 copies
    load_presplit<128>(sbase + A_OFF, sbase + AL_OFF, ArowH, ArowL, tid, K, 0);
    load_presplit<256>(sbase + BH_OFF, sbase + BL_OFF, BrowH, BrowL, tid, K, 0);
    CPCOMMIT();

    float acc[4][8][4];
#pragma unroll
    for (int mt = 0; mt < 4; mt++)
#pragma unroll
        for (int nt = 0; nt < 8; nt++)
#pragma unroll
            for (int q = 0; q < 4; q++) acc[mt][nt][q] = 0.f;

    for (int c = 0; c < NC; c++) {
        const int s = c & 1;
        const uint32_t sb = sbase + s * STAGE_B;

        CPWAIT0();
        __syncthreads();

        if (c + 1 < NC) {
            const uint32_t nb = sbase + (s ^ 1) * STAGE_B;
            const int k0 = (c + 1) * 64;
            load_presplit<128>(nb + A_OFF, nb + AL_OFF, ArowH, ArowL, tid, K, k0);
            load_presplit<256>(nb + BH_OFF, nb + BL_OFF, BrowH, BrowL, tid, K, k0);
            CPCOMMIT();
        }

        // compute chunk: 4 k16 steps; warp tile 64x64
#pragma unroll
        for (int k16 = 0; k16 < 4; k16++) {
            uint32_t ah[4][4], al[4][4], bh[4][4], bl[4][4];
#pragma unroll
            for (int mt = 0; mt < 4; mt++) {
                const int row = wm * 64 + mt * 16 + (lane & 15);
                const int kc  = k16 * 16 + (lane >> 4) * 8;
                const uint32_t off = (uint32_t)(row * 128) +
                                     (uint32_t)((kc * 2) ^ ((row & 7) << 4));
                LDSM4(ah[mt], sb + A_OFF + off);
                LDSM4(al[mt], sb + AL_OFF + off);
            }
#pragma unroll
            for (int p = 0; p < 4; p++) {
                const int g    = lane >> 3;
                const int nrow = wn * 64 + p * 16 + (g >> 1) * 8 + (lane & 7);
                const int kc   = k16 * 16 + (g & 1) * 8;
                const uint32_t off = (uint32_t)(nrow * 128) +
                                     (uint32_t)((kc * 2) ^ ((nrow & 7) << 4));
                LDSM4(bh[p], sb + BH_OFF + off);
                LDSM4(bl[p], sb + BL_OFF + off);
            }
#pragma unroll
            for (int mt = 0; mt < 4; mt++)
#pragma unroll
                for (int nt = 0; nt < 8; nt++) {
                    const int p = nt >> 1;
                    const int q = (nt & 1) * 2;
                    MMA_OP(acc[mt][nt], ah[mt], bh[p][q], bh[p][q + 1]);  // hi*hi
                    MMA_OP(acc[mt][nt], ah[mt], bl[p][q], bl[p][q + 1]);  // hi*lo
                    MMA_OP(acc[mt][nt], al[mt], bh[p][q], bh[p][q + 1]);  // lo*hi
                }
        }
        __syncthreads();
    }

    // ---- epilogue: warp covers rows [wm*64, wm*64+64), cols [wn*64, wn*64+64)
#pragma unroll
    for (int mt = 0; mt < 4; mt++)
#pragma unroll
        for (int half = 0; half < 2; half++) {
            const int r = m0 + wm * 64 + mt * 16 + (lane >> 2) + half * 8;
#pragma unroll
            for (int nt = 0; nt < 8; nt++) {
                const int col = n0 + wn * 64 + nt * 8 + (lane & 3) * 2;
                float vx = acc[mt][nt][half * 2];
                float vy = acc[mt][nt][half * 2 + 1];
                if (MODE == 1) {
                    const float2 bi = *(const float2*)(bias + col);
                    vx = gelu_exact(vx + bi.x);
                    vy = gelu_exact(vy + bi.y);
                    ep_split(g_h1h, g_h1l, (size_t)r * Av + col, vx, vy);
                } else if (MODE == 2) {
                    if (valid) {
                        const float2 bi = *(const float2*)(biasp + col);
                        vx += bi.x; vy += bi.y;
                    } else {
                        const size_t o = (size_t)r * Av + col;
                        uint32_t ph = *(const uint32_t*)(g_h1h + o);
                        uint32_t pl = *(const uint32_t*)(g_h1l + o);
                        float2 fh = __bfloat1622float2(*(__nv_bfloat162*)&ph);
                        float2 fl = __bfloat1622float2(*(__nv_bfloat162*)&pl);
                        vx = fh.x + fl.x;
                        vy = fh.y + fl.y;
                    }
                    const float2 em = *(const float2*)(embp + col);
                    vx += em.x; vy += em.y;
                    ep_split(g_h2h, g_h2l, (size_t)r * Av + col, vx, vy);
                } else {
                    const float2 bi = *(const float2*)(bias + col);
                    const float2 rs = *(const float2*)(extra + (size_t)r * Dv + col);
                    vx += bi.x + rs.x;
                    vy += bi.y + rs.y;
                    *(float2*)(g_pre + (size_t)r * N + col) = make_float2(vx, vy);
                }
            }
        }
}

// ---------------------------------------------------------------------------
// LayerNorm over D=1024 (one 256-thread block per row, 4 elems/thread)
// ---------------------------------------------------------------------------
__global__ __launch_bounds__(256)
void ln_kernel(const float* __restrict__ gamma,
               const float* __restrict__ beta,
               float* __restrict__ out) {
    const int row = blockIdx.x;
    const int t = threadIdx.x;
    const float4 v = *(const float4*)(g_pre + (size_t)row * Dv + t * 4);

    __shared__ float red1[8];
    __shared__ float red2[8];

    float s = v.x + v.y + v.z + v.w;
#pragma unroll
    for (int o = 16; o; o >>= 1) s += __shfl_xor_sync(0xFFFFFFFFu, s, o);
    if ((t & 31) == 0) red1[t >> 5] = s;
    __syncthreads();
    float tot = 0.f;
#pragma unroll
    for (int i = 0; i < 8; i++) tot += red1[i];
    const float mu = tot * (1.0f / Dv);

    const float dx = v.x - mu, dy = v.y - mu, dz = v.z - mu, dw = v.w - mu;
    float s2 = dx * dx + dy * dy + dz * dz + dw * dw;
#pragma unroll
    for (int o = 16; o; o >>= 1) s2 += __shfl_xor_sync(0xFFFFFFFFu, s2, o);
    if ((t & 31) == 0) red2[t >> 5] = s2;
    __syncthreads();
    float tot2 = 0.f;
#pragma unroll
    for (int i = 0; i < 8; i++) tot2 += red2[i];
    const float inv = rsqrtf(tot2 * (1.0f / Dv) + 1e-5f);

    const int c = t * 4;
    const float4 gm = *(const float4*)(gamma + c);
    const float4 bt = *(const float4*)(beta + c);
    float4 o;
    o.x = dx * inv * gm.x + bt.x;
    o.y = dy * inv * gm.y + bt.y;
    o.z = dz * inv * gm.z + bt.z;
    o.w = dw * inv * gm.w + bt.w;
    *(float4*)(out + (size_t)row * Dv + c) = o;
}

// ---------------------------------------------------------------------------
extern "C" void kernel_launch(void* const* d_in, const int* in_sizes, int n_in,
                              void* d_out, int out_size) {
    const float* hidden     = (const float*)d_in[0];
    const int*   dom        = (const int*)d_in[1];
    const float* down_W     = (const float*)d_in[2];
    const float* down_b     = (const float*)d_in[3];
    const float* up_W       = (const float*)d_in[4];
    const float* up_b       = (const float*)d_in[5];
    const float* expert_W   = (const float*)d_in[6];
    const float* expert_b   = (const float*)d_in[7];
    const float* domain_emb = (const float*)d_in[8];
    const float* gamma      = (const float*)d_in[9];
    const float* beta       = (const float*)d_in[10];
    float* out = (float*)d_out;

    cudaFuncSetAttribute(hmma_gemm<1>, cudaFuncAttributeMaxDynamicSharedMemorySize, SMEM_BYTES);
    cudaFuncSetAttribute(hmma_gemm<2>, cudaFuncAttributeMaxDynamicSharedMemorySize, SMEM_BYTES);
    cudaFuncSetAttribute(hmma_gemm<3>, cudaFuncAttributeMaxDynamicSharedMemorySize, SMEM_BYTES);

    prep_ids<<<1, 1>>>(dom);

    // one-time splits (weights + hidden input)
    __nv_bfloat16 *dwh, *dwl, *uwh, *uwl, *ewh, *ewl, *xh, *xl;
    cudaGetSymbolAddress((void**)&dwh, g_dwh);
    cudaGetSymbolAddress((void**)&dwl, g_dwl);
    cudaGetSymbolAddress((void**)&uwh, g_uwh);
    cudaGetSymbolAddress((void**)&uwl, g_uwl);
    cudaGetSymbolAddress((void**)&ewh, g_ewh);
    cudaGetSymbolAddress((void**)&ewl, g_ewl);
    cudaGetSymbolAddress((void**)&xh, g_xh);
    cudaGetSymbolAddress((void**)&xl, g_xl);
    split_w<<<128, 512>>>(down_W, dwh, dwl, Av * Dv / 4);
    split_w<<<128, 512>>>(up_W, uwh, uwl, Dv * Av / 4);
    split_w<<<256, 512>>>(expert_W, ewh, ewl, Ev * Av * Av / 4);
    split_w<<<2048, 512>>>(hidden, xh, xl, Mrows * Dv / 4);

    // Stage 1: down-proj + GELU   (M=32768, N=256,  K=1024)
    hmma_gemm<1><<<dim3(1, Mrows / 128), 256, SMEM_BYTES>>>(down_b, nullptr);
    // Stage 2: per-batch expert   (per batch M=1024, N=256, K=256)
    hmma_gemm<2><<<dim3(1, Sv / 128, Bv), 256, SMEM_BYTES>>>(expert_b, domain_emb);
    // Stage 3: up-proj + residual (M=32768, N=1024, K=256)
    hmma_gemm<3><<<dim3(Dv / 256, Mrows / 128), 256, SMEM_BYTES>>>(up_b, hidden);
    // Stage 4: LayerNorm
    ln_kernel<<<Mrows, 256>>>(gamma, beta, out);
}

// round 7
// speedup vs baseline: 1.3633x; 1.3633x over previous
#include <cuda_runtime.h>
#include <cuda_fp16.h>
#include <math.h>
#include <stdint.h>

// Problem dims (fixed)
#define Bv 32
#define Sv 1024
#define Dv 1024
#define Av 256
#define Ev 16
#define Mrows (Bv * Sv)   // 32768

// ---------------------------------------------------------------------------
// Persistent scratch (no cudaMalloc allowed)
// ---------------------------------------------------------------------------
__device__ float g_pre[(size_t)Mrows * Dv];          // pre-LN fp32
__device__ __half g_h1h[(size_t)Mrows * Av];         // stage1 out hi
__device__ __half g_h1l[(size_t)Mrows * Av];         // stage1 out lo
__device__ __half g_h2h[(size_t)Mrows * Av];         // stage2 out hi
__device__ __half g_h2l[(size_t)Mrows * Av];         // stage2 out lo
__device__ __half g_dwh[Av * Dv];                    // down_W fp16 hi
__device__ __half g_uwh[Dv * Av];                    // up_W fp16 hi
__device__ __half g_ewh[Ev * Av * Av];               // expert_W fp16 hi
__device__ int g_idx[Bv];
__device__ int g_valid[Bv];

// ---------------------------------------------------------------------------
__device__ __forceinline__ uint32_t smem_u32(const void* p) {
    uint32_t a;
    asm("{ .reg .u64 t; cvta.to.shared.u64 t, %1; cvt.u32.u64 %0, t; }" : "=r"(a) : "l"(p));
    return a;
}
#define LDSM4(r, addr) \
    asm volatile("ldmatrix.sync.aligned.m8n8.x4.shared.b16 {%0,%1,%2,%3}, [%4];" \
        : "=r"((r)[0]), "=r"((r)[1]), "=r"((r)[2]), "=r"((r)[3]) : "r"(addr))
#define MMA_OP(d, a, b0, b1) \
    asm volatile("mma.sync.aligned.m16n8k16.row.col.f32.f16.f16.f32 " \
        "{%0,%1,%2,%3}, {%4,%5,%6,%7}, {%8,%9}, {%0,%1,%2,%3};" \
        : "+f"((d)[0]), "+f"((d)[1]), "+f"((d)[2]), "+f"((d)[3]) \
        : "r"((a)[0]), "r"((a)[1]), "r"((a)[2]), "r"((a)[3]), "r"(b0), "r"(b1))
#define CP16(dst, src) \
    asm volatile("cp.async.cg.shared.global [%0], [%1], 16;" :: "r"(dst), "l"(src))
#define CPCOMMIT() asm volatile("cp.async.commit_group;" ::: "memory")
#define CPWAIT0()  asm volatile("cp.async.wait_group 0;" ::: "memory")

// ---------------------------------------------------------------------------
// domain_id may arrive as int32 or int64. Detect and normalize.
// ---------------------------------------------------------------------------
__global__ void prep_ids(const int* __restrict__ p) {
    bool is64 = true;
    for (int k = 0; k < 16; k++) {
        int hi = p[2 * k + 1];
        if (hi != 0 && hi != -1) { is64 = false; break; }
    }
    for (int b = 0; b < Bv; b++) {
        long long v;
        if (is64) {
            unsigned int lo = (unsigned int)p[2 * b];
            int hi = p[2 * b + 1];
            v = ((long long)hi << 32) | (long long)lo;
        } else {
            v = p[b];
        }
        g_valid[b] = (v >= 0 && v < Ev) ? 1 : 0;
        long long c = v < 0 ? 0 : (v > (Ev - 1) ? (Ev - 1) : v);
        g_idx[b] = (int)c;
    }
}

// Convert fp32 weights to fp16 (hi only), vectorized float4 -> 4 halves.
__global__ void conv_w(const float* __restrict__ src,
                       __half* __restrict__ H, int n4) {
    for (int i = blockIdx.x * blockDim.x + threadIdx.x; i < n4;
         i += gridDim.x * blockDim.x) {
        float4 v = ((const float4*)src)[i];
        __half2 h0 = __floats2half2_rn(v.x, v.y);
        __half2 h1 = __floats2half2_rn(v.z, v.w);
        ((uint2*)H)[i] = make_uint2(*(uint32_t*)&h0, *(uint32_t*)&h1);
    }
}

__device__ __forceinline__ float gelu_exact(float v) {
    return 0.5f * v * (1.0f + erff(v * 0.70710678118654752440f));
}

// Split fp32 float4 into hi/lo fp16 pairs and store 8B each (swizzle-safe).
__device__ __forceinline__ void split_store(char* hi_base, char* lo_base,
                                            uint32_t off, float4 v) {
    __half2 h0 = __floats2half2_rn(v.x, v.y);
    __half2 h1 = __floats2half2_rn(v.z, v.w);
    float2 f0 = __half22float2(h0);
    float2 f1 = __half22float2(h1);
    __half2 l0 = __floats2half2_rn(v.x - f0.x, v.y - f0.y);
    __half2 l1 = __floats2half2_rn(v.z - f1.x, v.w - f1.y);
    *(uint2*)(hi_base + off) = make_uint2(*(uint32_t*)&h0, *(uint32_t*)&h1);
    *(uint2*)(lo_base + off) = make_uint2(*(uint32_t*)&l0, *(uint32_t*)&l1);
}

// Epilogue split-write of a float2 into hi/lo fp16 arrays.
__device__ __forceinline__ void ep_split(__half* H, __half* L,
                                         size_t off, float x, float y) {
    __half2 h = __floats2half2_rn(x, y);
    float2 hf = __half22float2(h);
    __half2 l = __floats2half2_rn(x - hf.x, y - hf.y);
    *(uint32_t*)(H + off) = *(uint32_t*)&h;
    *(uint32_t*)(L + off) = *(uint32_t*)&l;
}

// cp.async loaders into swizzled SMEM (512 threads).
// 128-row pair (hi+lo): 1024 lines of 16B per half -> 2 iters.
__device__ __forceinline__ void load_pair128(uint32_t dstHi, uint32_t dstLo,
                                             const __half* __restrict__ hi,
                                             const __half* __restrict__ lo,
                                             int tid, int K, int k0) {
#pragma unroll
    for (int i = 0; i < 2; i++) {
        const int idx = tid + i * 512;
        const int row = idx >> 3;
        const int c8 = idx & 7;
        const uint32_t off = (uint32_t)(row * 128) +
                             (uint32_t)((c8 * 16) ^ ((row & 7) << 4));
        const size_t g = (size_t)row * K + k0 + c8 * 8;
        CP16(dstHi + off, hi + g);
        CP16(dstLo + off, lo + g);
    }
}
// 256-row hi-only: 2048 lines -> 4 iters.
__device__ __forceinline__ void load_hi256(uint32_t dst,
                                           const __half* __restrict__ hi,
                                           int tid, int K, int k0) {
#pragma unroll
    for (int i = 0; i < 4; i++) {
        const int idx = tid + i * 512;
        const int row = idx >> 3;
        const int c8 = idx & 7;
        const uint32_t off = (uint32_t)(row * 128) +
                             (uint32_t)((c8 * 16) ^ ((row & 7) << 4));
        CP16(dst + off, hi + (size_t)row * K + k0 + c8 * 8);
    }
}

// ---------------------------------------------------------------------------
// fp16 2-pass split NT GEMM via mma.sync: C[128,256] = A[M,K] * B[N,K]^T
//   A = Ah + Al (fp16 hi/lo), B ~ Bh (fp16 hi); C = Ah*Bh + Al*Bh.
// 512 threads, 16 warps 4(M)x4(N); warp tile 32x64 (mt=2 x nt=8).
// BK=64, 2-stage cp.async. SMEM stage: Ah(16K) Al(16K) Bh(32K) = 64KB; x2.
// MODE 1: A = hidden fp32 (in-loop reg split), B = down_W; GELU -> g_h1h/l
// MODE 2: A = g_h1, B = expert_W[e]; +bias/pass + emb -> g_h2h/l
// MODE 3: A = g_h2, B = up_W; +bias+residual -> g_pre fp32
// ---------------------------------------------------------------------------
#define A_OFF 0u
#define AL_OFF 16384u
#define BH_OFF 32768u
#define STAGE_B 65536u
#define SMEM_BYTES (2u * STAGE_B)

template <int MODE>
__global__ __launch_bounds__(512, 1)
void hmma_gemm(const float* __restrict__ Afp,
               const float* __restrict__ bias,
               const float* __restrict__ extra) {
    constexpr int K  = (MODE == 1) ? Dv : Av;
    constexpr int N  = (MODE == 3) ? Dv : Av;
    constexpr int NC = K / 64;

    extern __shared__ char sm[];
    const uint32_t sbase = smem_u32(sm);

    const int tid  = threadIdx.x;
    const int lane = tid & 31;
    const int wid  = tid >> 5;
    const int wm   = wid & 3;     // warp row: 4 x 32 = 128 M
    const int wn   = wid >> 2;    // warp col: 4 x 64 = 256 N

    int m0;
    const int n0 = blockIdx.x * 256;
    const __half *Ah = nullptr, *Al = nullptr, *Bh;
    const float* biasp = bias;
    const float* embp = nullptr;
    int valid = 1;
    if (MODE == 1) {
        m0 = blockIdx.y * 128;
        Bh = g_dwh;
    } else if (MODE == 2) {
        const int b = blockIdx.z;
        const int e = g_idx[b];
        valid = g_valid[b];
        m0 = b * Sv + blockIdx.y * 128;
        Ah = g_h1h; Al = g_h1l;
        Bh = g_ewh + (size_t)e * Av * Av;
        biasp = bias + (size_t)e * Av;
        embp = extra + (size_t)e * Av;
    } else {
        m0 = blockIdx.y * 128;
        Ah = g_h2h; Al = g_h2l;
        Bh = g_uwh;
    }

    const float* ArowF = (MODE == 1) ? (Afp + (size_t)m0 * K) : nullptr;
    const __half* ArowH = (MODE != 1) ? (Ah + (size_t)m0 * K) : nullptr;
    const __half* ArowL = (MODE != 1) ? (Al + (size_t)m0 * K) : nullptr;
    const __half* BrowH = Bh + (size_t)n0 * K;

    // MODE1 A register-split coords (128x64 fp32 -> 2048 float4, 4/thread)
    int lr[4], lc[4];
    uint32_t soff[4];
    float4 pA[4];
    if (MODE == 1) {
#pragma unroll
        for (int i = 0; i < 4; i++) {
            const int idx = tid + i * 512;
            lr[i] = idx >> 4;
            lc[i] = (idx & 15) * 4;
            soff[i] = (uint32_t)(lr[i] * 128) +
                      (uint32_t)((lc[i] * 2) ^ ((lr[i] & 7) << 4));
            pA[i] = *(const float4*)(ArowF + (size_t)lr[i] * K + lc[i]);
        }
    }

    // Prologue: issue chunk 0 copies
    {
        if (MODE != 1)
            load_pair128(sbase + A_OFF, sbase + AL_OFF, ArowH, ArowL, tid, K, 0);
        load_hi256(sbase + BH_OFF, BrowH, tid, K, 0);
        CPCOMMIT();
    }

    float acc[2][8][4];
#pragma unroll
    for (int mt = 0; mt < 2; mt++)
#pragma unroll
        for (int nt = 0; nt < 8; nt++)
#pragma unroll
            for (int q = 0; q < 4; q++) acc[mt][nt][q] = 0.f;

    for (int c = 0; c < NC; c++) {
        const int s = c & 1;
        const uint32_t sb = sbase + s * STAGE_B;

        if (MODE == 1) {
            char* smc = sm + s * STAGE_B;
#pragma unroll
            for (int i = 0; i < 4; i++)
                split_store(smc + A_OFF, smc + AL_OFF, soff[i], pA[i]);
        }
        CPWAIT0();
        __syncthreads();

        if (c + 1 < NC) {
            const uint32_t nb = sbase + (s ^ 1) * STAGE_B;
            const int k0 = (c + 1) * 64;
            if (MODE != 1)
                load_pair128(nb + A_OFF, nb + AL_OFF, ArowH, ArowL, tid, K, k0);
            load_hi256(nb + BH_OFF, BrowH, tid, K, k0);
            CPCOMMIT();
            if (MODE == 1) {
#pragma unroll
                for (int i = 0; i < 4; i++)
                    pA[i] = *(const float4*)(ArowF + (size_t)lr[i] * K + k0 + lc[i]);
            }
        }

        // compute chunk: 4 k16 steps x 2 passes, warp tile 32x64
#pragma unroll
        for (int k16 = 0; k16 < 4; k16++) {
            uint32_t ah[2][4], al[2][4], bh[4][4];
#pragma unroll
            for (int mt = 0; mt < 2; mt++) {
                const int row = wm * 32 + mt * 16 + (lane & 15);
                const int kc  = k16 * 16 + (lane >> 4) * 8;
                const uint32_t off = (uint32_t)(row * 128) +
                                     (uint32_t)((kc * 2) ^ ((row & 7) << 4));
                LDSM4(ah[mt], sb + A_OFF + off);
                LDSM4(al[mt], sb + AL_OFF + off);
            }
#pragma unroll
            for (int p = 0; p < 4; p++) {
                const int g    = lane >> 3;
                const int nrow = wn * 64 + p * 16 + (g >> 1) * 8 + (lane & 7);
                const int kc   = k16 * 16 + (g & 1) * 8;
                const uint32_t off = (uint32_t)(nrow * 128) +
                                     (uint32_t)((kc * 2) ^ ((nrow & 7) << 4));
                LDSM4(bh[p], sb + BH_OFF + off);
            }
#pragma unroll
            for (int mt = 0; mt < 2; mt++)
#pragma unroll
                for (int nt = 0; nt < 8; nt++) {
                    const int p = nt >> 1;
                    const int q = (nt & 1) * 2;
                    MMA_OP(acc[mt][nt], ah[mt], bh[p][q], bh[p][q + 1]);  // hi*Bh
                    MMA_OP(acc[mt][nt], al[mt], bh[p][q], bh[p][q + 1]);  // lo*Bh
                }
        }
        __syncthreads();
    }

    // ---- epilogue ----
#pragma unroll
    for (int mt = 0; mt < 2; mt++)
#pragma unroll
        for (int half = 0; half < 2; half++) {
            const int r = m0 + wm * 32 + mt * 16 + (lane >> 2) + half * 8;
#pragma unroll
            for (int nt = 0; nt < 8; nt++) {
                const int col = n0 + wn * 64 + nt * 8 + (lane & 3) * 2;
                float vx = acc[mt][nt][half * 2];
                float vy = acc[mt][nt][half * 2 + 1];
                if (MODE == 1) {
                    const float2 bi = *(const float2*)(bias + col);
                    vx = gelu_exact(vx + bi.x);
                    vy = gelu_exact(vy + bi.y);
                    ep_split(g_h1h, g_h1l, (size_t)r * Av + col, vx, vy);
                } else if (MODE == 2) {
                    if (valid) {
                        const float2 bi = *(const float2*)(biasp + col);
                        vx += bi.x; vy += bi.y;
                    } else {
                        const size_t o = (size_t)r * Av + col;
                        uint32_t ph = *(const uint32_t*)(g_h1h + o);
                        uint32_t pl = *(const uint32_t*)(g_h1l + o);
                        float2 fh = __half22float2(*(__half2*)&ph);
                        float2 fl = __half22float2(*(__half2*)&pl);
                        vx = fh.x + fl.x;
                        vy = fh.y + fl.y;
                    }
                    const float2 em = *(const float2*)(embp + col);
                    vx += em.x; vy += em.y;
                    ep_split(g_h2h, g_h2l, (size_t)r * Av + col, vx, vy);
                } else {
                    const float2 bi = *(const float2*)(bias + col);
                    const float2 rs = *(const float2*)(extra + (size_t)r * Dv + col);
                    vx += bi.x + rs.x;
                    vy += bi.y + rs.y;
                    *(float2*)(g_pre + (size_t)r * N + col) = make_float2(vx, vy);
                }
            }
        }
}

// ---------------------------------------------------------------------------
// LayerNorm over D=1024 (one 256-thread block per row, 4 elems/thread)
// ---------------------------------------------------------------------------
__global__ __launch_bounds__(256)
void ln_kernel(const float* __restrict__ gamma,
               const float* __restrict__ beta,
               float* __restrict__ out) {
    const int row = blockIdx.x;
    const int t = threadIdx.x;
    const float4 v = *(const float4*)(g_pre + (size_t)row * Dv + t * 4);

    __shared__ float red1[8];
    __shared__ float red2[8];

    float s = v.x + v.y + v.z + v.w;
#pragma unroll
    for (int o = 16; o; o >>= 1) s += __shfl_xor_sync(0xFFFFFFFFu, s, o);
    if ((t & 31) == 0) red1[t >> 5] = s;
    __syncthreads();
    float tot = 0.f;
#pragma unroll
    for (int i = 0; i < 8; i++) tot += red1[i];
    const float mu = tot * (1.0f / Dv);

    const float dx = v.x - mu, dy = v.y - mu, dz = v.z - mu, dw = v.w - mu;
    float s2 = dx * dx + dy * dy + dz * dz + dw * dw;
#pragma unroll
    for (int o = 16; o; o >>= 1) s2 += __shfl_xor_sync(0xFFFFFFFFu, s2, o);
    if ((t & 31) == 0) red2[t >> 5] = s2;
    __syncthreads();
    float tot2 = 0.f;
#pragma unroll
    for (int i = 0; i < 8; i++) tot2 += red2[i];
    const float inv = rsqrtf(tot2 * (1.0f / Dv) + 1e-5f);

    const int c = t * 4;
    const float4 gm = *(const float4*)(gamma + c);
    const float4 bt = *(const float4*)(beta + c);
    float4 o;
    o.x = dx * inv * gm.x + bt.x;
    o.y = dy * inv * gm.y + bt.y;
    o.z = dz * inv * gm.z + bt.z;
    o.w = dw * inv * gm.w + bt.w;
    *(float4*)(out + (size_t)row * Dv + c) = o;
}

// ---------------------------------------------------------------------------
extern "C" void kernel_launch(void* const* d_in, const int* in_sizes, int n_in,
                              void* d_out, int out_size) {
    const float* hidden     = (const float*)d_in[0];
    const int*   dom        = (const int*)d_in[1];
    const float* down_W     = (const float*)d_in[2];
    const float* down_b     = (const float*)d_in[3];
    const float* up_W       = (const float*)d_in[4];
    const float* up_b       = (const float*)d_in[5];
    const float* expert_W   = (const float*)d_in[6];
    const float* expert_b   = (const float*)d_in[7];
    const float* domain_emb = (const float*)d_in[8];
    const float* gamma      = (const float*)d_in[9];
    const float* beta       = (const float*)d_in[10];
    float* out = (float*)d_out;

    cudaFuncSetAttribute(hmma_gemm<1>, cudaFuncAttributeMaxDynamicSharedMemorySize, SMEM_BYTES);
    cudaFuncSetAttribute(hmma_gemm<2>, cudaFuncAttributeMaxDynamicSharedMemorySize, SMEM_BYTES);
    cudaFuncSetAttribute(hmma_gemm<3>, cudaFuncAttributeMaxDynamicSharedMemorySize, SMEM_BYTES);

    prep_ids<<<1, 1>>>(dom);

    // one-time weight conversions (fp16 hi only)
    __half *dwh, *uwh, *ewh;
    cudaGetSymbolAddress((void**)&dwh, g_dwh);
    cudaGetSymbolAddress((void**)&uwh, g_uwh);
    cudaGetSymbolAddress((void**)&ewh, g_ewh);
    conv_w<<<128, 512>>>(down_W, dwh, Av * Dv / 4);
    conv_w<<<128, 512>>>(up_W, uwh, Dv * Av / 4);
    conv_w<<<256, 512>>>(expert_W, ewh, Ev * Av * Av / 4);

    // Stage 1: down-proj + GELU   (M=32768, N=256,  K=1024)
    hmma_gemm<1><<<dim3(1, Mrows / 128), 512, SMEM_BYTES>>>(hidden, down_b, nullptr);
    // Stage 2: per-batch expert   (per batch M=1024, N=256, K=256)
    hmma_gemm<2><<<dim3(1, Sv / 128, Bv), 512, SMEM_BYTES>>>(nullptr, expert_b, domain_emb);
    // Stage 3: up-proj + residual (M=32768, N=1024, K=256)
    hmma_gemm<3><<<dim3(Dv / 256, Mrows / 128), 512, SMEM_BYTES>>>(nullptr, up_b, hidden);
    // Stage 4: LayerNorm
    ln_kernel<<<Mrows, 256>>>(gamma, beta, out);
}

// round 8
// speedup vs baseline: 1.9443x; 1.4261x over previous
#include <cuda_runtime.h>
#include <cuda_fp16.h>
#include <math.h>
#include <stdint.h>

// Problem dims (fixed)
#define Bv 32
#define Sv 1024
#define Dv 1024
#define Av 256
#define Ev 16
#define Mrows (Bv * Sv)   // 32768

// ---------------------------------------------------------------------------
// Persistent scratch (no cudaMalloc allowed)
// ---------------------------------------------------------------------------
__device__ float g_pre[(size_t)Mrows * Dv];          // pre-LN fp32
__device__ __half g_h1[(size_t)Mrows * Av];          // stage1 out fp16
__device__ __half g_h2[(size_t)Mrows * Av];          // stage2 out fp16
__device__ __half g_dwh[Av * Dv];                    // down_W fp16
__device__ __half g_uwh[Dv * Av];                    // up_W fp16
__device__ __half g_ewh[Ev * Av * Av];               // expert_W fp16
__device__ int g_idx[Bv];
__device__ int g_valid[Bv];

// ---------------------------------------------------------------------------
__device__ __forceinline__ uint32_t smem_u32(const void* p) {
    uint32_t a;
    asm("{ .reg .u64 t; cvta.to.shared.u64 t, %1; cvt.u32.u64 %0, t; }" : "=r"(a) : "l"(p));
    return a;
}
#define LDSM4(r, addr) \
    asm volatile("ldmatrix.sync.aligned.m8n8.x4.shared.b16 {%0,%1,%2,%3}, [%4];" \
        : "=r"((r)[0]), "=r"((r)[1]), "=r"((r)[2]), "=r"((r)[3]) : "r"(addr))
#define MMA_OP(d, a, b0, b1) \
    asm volatile("mma.sync.aligned.m16n8k16.row.col.f32.f16.f16.f32 " \
        "{%0,%1,%2,%3}, {%4,%5,%6,%7}, {%8,%9}, {%0,%1,%2,%3};" \
        : "+f"((d)[0]), "+f"((d)[1]), "+f"((d)[2]), "+f"((d)[3]) \
        : "r"((a)[0]), "r"((a)[1]), "r"((a)[2]), "r"((a)[3]), "r"(b0), "r"(b1))
#define CP16(dst, src) \
    asm volatile("cp.async.cg.shared.global [%0], [%1], 16;" :: "r"(dst), "l"(src))
#define CPCOMMIT() asm volatile("cp.async.commit_group;" ::: "memory")
#define CPWAIT0()  asm volatile("cp.async.wait_group 0;" ::: "memory")

// ---------------------------------------------------------------------------
// domain_id may arrive as int32 or int64. Detect and normalize.
// ---------------------------------------------------------------------------
__global__ void prep_ids(const int* __restrict__ p) {
    bool is64 = true;
    for (int k = 0; k < 16; k++) {
        int hi = p[2 * k + 1];
        if (hi != 0 && hi != -1) { is64 = false; break; }
    }
    for (int b = 0; b < Bv; b++) {
        long long v;
        if (is64) {
            unsigned int lo = (unsigned int)p[2 * b];
            int hi = p[2 * b + 1];
            v = ((long long)hi << 32) | (long long)lo;
        } else {
            v = p[b];
        }
        g_valid[b] = (v >= 0 && v < Ev) ? 1 : 0;
        long long c = v < 0 ? 0 : (v > (Ev - 1) ? (Ev - 1) : v);
        g_idx[b] = (int)c;
    }
}

// Convert fp32 weights to fp16, vectorized float4 -> 4 halves.
__global__ void conv_w(const float* __restrict__ src,
                       __half* __restrict__ H, int n4) {
    for (int i = blockIdx.x * blockDim.x + threadIdx.x; i < n4;
         i += gridDim.x * blockDim.x) {
        float4 v = ((const float4*)src)[i];
        __half2 h0 = __floats2half2_rn(v.x, v.y);
        __half2 h1 = __floats2half2_rn(v.z, v.w);
        ((uint2*)H)[i] = make_uint2(*(uint32_t*)&h0, *(uint32_t*)&h1);
    }
}

__device__ __forceinline__ float gelu_exact(float v) {
    return 0.5f * v * (1.0f + erff(v * 0.70710678118654752440f));
}

// Convert fp32 float4 -> 4 fp16, store 8B (swizzle-safe).
__device__ __forceinline__ void conv_store(char* base, uint32_t off, float4 v) {
    __half2 h0 = __floats2half2_rn(v.x, v.y);
    __half2 h1 = __floats2half2_rn(v.z, v.w);
    *(uint2*)(base + off) = make_uint2(*(uint32_t*)&h0, *(uint32_t*)&h1);
}

// cp.async loaders into swizzled SMEM (512 threads).
// 128-row fp16 tile: 1024 lines of 16B -> 2 iters.
__device__ __forceinline__ void load_hi128(uint32_t dst,
                                           const __half* __restrict__ hi,
                                           int tid, int K, int k0) {
#pragma unroll
    for (int i = 0; i < 2; i++) {
        const int idx = tid + i * 512;
        const int row = idx >> 3;
        const int c8 = idx & 7;
        const uint32_t off = (uint32_t)(row * 128) +
                             (uint32_t)((c8 * 16) ^ ((row & 7) << 4));
        CP16(dst + off, hi + (size_t)row * K + k0 + c8 * 8);
    }
}
// 256-row fp16 tile: 2048 lines -> 4 iters.
__device__ __forceinline__ void load_hi256(uint32_t dst,
                                           const __half* __restrict__ hi,
                                           int tid, int K, int k0) {
#pragma unroll
    for (int i = 0; i < 4; i++) {
        const int idx = tid + i * 512;
        const int row = idx >> 3;
        const int c8 = idx & 7;
        const uint32_t off = (uint32_t)(row * 128) +
                             (uint32_t)((c8 * 16) ^ ((row & 7) << 4));
        CP16(dst + off, hi + (size_t)row * K + k0 + c8 * 8);
    }
}

// ---------------------------------------------------------------------------
// fp16 NT GEMM via mma.sync: C[128,256] = A[M,K] * B[N,K]^T, fp32 accum.
// 512 threads, 16 warps 4(M)x4(N); warp tile 32x64 (mt=2 x nt=8).
// BK=64, 2-stage cp.async. SMEM stage: A(16K) B(32K) = 48KB; x2 = 96KB.
// MODE 1: A = hidden fp32 (in-loop convert), B = down_W; GELU -> g_h1
// MODE 2: A = g_h1, B = expert_W[e]; +bias/pass + emb -> g_h2
// MODE 3: A = g_h2, B = up_W; +bias+residual -> g_pre fp32
// ---------------------------------------------------------------------------
#define A_OFF 0u
#define BH_OFF 16384u
#define STAGE_B 49152u
#define SMEM_BYTES (2u * STAGE_B)

template <int MODE>
__global__ __launch_bounds__(512, 1)
void hmma_gemm(const float* __restrict__ Afp,
               const float* __restrict__ bias,
               const float* __restrict__ extra) {
    constexpr int K  = (MODE == 1) ? Dv : Av;
    constexpr int N  = (MODE == 3) ? Dv : Av;
    constexpr int NC = K / 64;

    extern __shared__ char sm[];
    const uint32_t sbase = smem_u32(sm);

    const int tid  = threadIdx.x;
    const int lane = tid & 31;
    const int wid  = tid >> 5;
    const int wm   = wid & 3;     // warp row: 4 x 32 = 128 M
    const int wn   = wid >> 2;    // warp col: 4 x 64 = 256 N

    int m0;
    const int n0 = blockIdx.x * 256;
    const __half *Ah = nullptr, *Bh;
    const float* biasp = bias;
    const float* embp = nullptr;
    int valid = 1;
    if (MODE == 1) {
        m0 = blockIdx.y * 128;
        Bh = g_dwh;
    } else if (MODE == 2) {
        const int b = blockIdx.z;
        const int e = g_idx[b];
        valid = g_valid[b];
        m0 = b * Sv + blockIdx.y * 128;
        Ah = g_h1;
        Bh = g_ewh + (size_t)e * Av * Av;
        biasp = bias + (size_t)e * Av;
        embp = extra + (size_t)e * Av;
    } else {
        m0 = blockIdx.y * 128;
        Ah = g_h2;
        Bh = g_uwh;
    }

    const float* ArowF = (MODE == 1) ? (Afp + (size_t)m0 * K) : nullptr;
    const __half* ArowH = (MODE != 1) ? (Ah + (size_t)m0 * K) : nullptr;
    const __half* BrowH = Bh + (size_t)n0 * K;

    // MODE1 A convert coords (128x64 fp32 -> 2048 float4, 4/thread)
    int lr[4], lc[4];
    uint32_t soff[4];
    float4 pA[4];
    if (MODE == 1) {
#pragma unroll
        for (int i = 0; i < 4; i++) {
            const int idx = tid + i * 512;
            lr[i] = idx >> 4;
            lc[i] = (idx & 15) * 4;
            soff[i] = (uint32_t)(lr[i] * 128) +
                      (uint32_t)((lc[i] * 2) ^ ((lr[i] & 7) << 4));
            pA[i] = *(const float4*)(ArowF + (size_t)lr[i] * K + lc[i]);
        }
    }

    // Prologue: issue chunk 0 copies
    {
        if (MODE != 1) load_hi128(sbase + A_OFF, ArowH, tid, K, 0);
        load_hi256(sbase + BH_OFF, BrowH, tid, K, 0);
        CPCOMMIT();
    }

    float acc[2][8][4];
#pragma unroll
    for (int mt = 0; mt < 2; mt++)
#pragma unroll
        for (int nt = 0; nt < 8; nt++)
#pragma unroll
            for (int q = 0; q < 4; q++) acc[mt][nt][q] = 0.f;

    for (int c = 0; c < NC; c++) {
        const int s = c & 1;
        const uint32_t sb = sbase + s * STAGE_B;

        if (MODE == 1) {
            char* smc = sm + s * STAGE_B;
#pragma unroll
            for (int i = 0; i < 4; i++)
                conv_store(smc + A_OFF, soff[i], pA[i]);
        }
        CPWAIT0();
        __syncthreads();

        if (c + 1 < NC) {
            const uint32_t nb = sbase + (s ^ 1) * STAGE_B;
            const int k0 = (c + 1) * 64;
            if (MODE != 1) load_hi128(nb + A_OFF, ArowH, tid, K, k0);
            load_hi256(nb + BH_OFF, BrowH, tid, K, k0);
            CPCOMMIT();
            if (MODE == 1) {
#pragma unroll
                for (int i = 0; i < 4; i++)
                    pA[i] = *(const float4*)(ArowF + (size_t)lr[i] * K + k0 + lc[i]);
            }
        }

        // compute chunk: 4 k16 steps, warp tile 32x64
#pragma unroll
        for (int k16 = 0; k16 < 4; k16++) {
            uint32_t ah[2][4], bh[4][4];
#pragma unroll
            for (int mt = 0; mt < 2; mt++) {
                const int row = wm * 32 + mt * 16 + (lane & 15);
                const int kc  = k16 * 16 + (lane >> 4) * 8;
                const uint32_t off = (uint32_t)(row * 128) +
                                     (uint32_t)((kc * 2) ^ ((row & 7) << 4));
                LDSM4(ah[mt], sb + A_OFF + off);
            }
#pragma unroll
            for (int p = 0; p < 4; p++) {
                const int g    = lane >> 3;
                const int nrow = wn * 64 + p * 16 + (g >> 1) * 8 + (lane & 7);
                const int kc   = k16 * 16 + (g & 1) * 8;
                const uint32_t off = (uint32_t)(nrow * 128) +
                                     (uint32_t)((kc * 2) ^ ((nrow & 7) << 4));
                LDSM4(bh[p], sb + BH_OFF + off);
            }
#pragma unroll
            for (int mt = 0; mt < 2; mt++)
#pragma unroll
                for (int nt = 0; nt < 8; nt++) {
                    const int p = nt >> 1;
                    const int q = (nt & 1) * 2;
                    MMA_OP(acc[mt][nt], ah[mt], bh[p][q], bh[p][q + 1]);
                }
        }
        __syncthreads();
    }

    // ---- epilogue ----
#pragma unroll
    for (int mt = 0; mt < 2; mt++)
#pragma unroll
        for (int half = 0; half < 2; half++) {
            const int r = m0 + wm * 32 + mt * 16 + (lane >> 2) + half * 8;
#pragma unroll
            for (int nt = 0; nt < 8; nt++) {
                const int col = n0 + wn * 64 + nt * 8 + (lane & 3) * 2;
                float vx = acc[mt][nt][half * 2];
                float vy = acc[mt][nt][half * 2 + 1];
                if (MODE == 1) {
                    const float2 bi = *(const float2*)(bias + col);
                    vx = gelu_exact(vx + bi.x);
                    vy = gelu_exact(vy + bi.y);
                    __half2 h = __floats2half2_rn(vx, vy);
                    *(uint32_t*)(g_h1 + (size_t)r * Av + col) = *(uint32_t*)&h;
                } else if (MODE == 2) {
                    if (valid) {
                        const float2 bi = *(const float2*)(biasp + col);
                        vx += bi.x; vy += bi.y;
                    } else {
                        uint32_t ph = *(const uint32_t*)(g_h1 + (size_t)r * Av + col);
                        float2 fh = __half22float2(*(__half2*)&ph);
                        vx = fh.x; vy = fh.y;
                    }
                    const float2 em = *(const float2*)(embp + col);
                    vx += em.x; vy += em.y;
                    __half2 h = __floats2half2_rn(vx, vy);
                    *(uint32_t*)(g_h2 + (size_t)r * Av + col) = *(uint32_t*)&h;
                } else {
                    const float2 bi = *(const float2*)(bias + col);
                    const float2 rs = *(const float2*)(extra + (size_t)r * Dv + col);
                    vx += bi.x + rs.x;
                    vy += bi.y + rs.y;
                    *(float2*)(g_pre + (size_t)r * N + col) = make_float2(vx, vy);
                }
            }
        }
}

// ---------------------------------------------------------------------------
// LayerNorm over D=1024 (one 256-thread block per row, 4 elems/thread)
// ---------------------------------------------------------------------------
__global__ __launch_bounds__(256)
void ln_kernel(const float* __restrict__ gamma,
               const float* __restrict__ beta,
               float* __restrict__ out) {
    const int row = blockIdx.x;
    const int t = threadIdx.x;
    const float4 v = *(const float4*)(g_pre + (size_t)row * Dv + t * 4);

    __shared__ float red1[8];
    __shared__ float red2[8];

    float s = v.x + v.y + v.z + v.w;
#pragma unroll
    for (int o = 16; o; o >>= 1) s += __shfl_xor_sync(0xFFFFFFFFu, s, o);
    if ((t & 31) == 0) red1[t >> 5] = s;
    __syncthreads();
    float tot = 0.f;
#pragma unroll
    for (int i = 0; i < 8; i++) tot += red1[i];
    const float mu = tot * (1.0f / Dv);

    const float dx = v.x - mu, dy = v.y - mu, dz = v.z - mu, dw = v.w - mu;
    float s2 = dx * dx + dy * dy + dz * dz + dw * dw;
#pragma unroll
    for (int o = 16; o; o >>= 1) s2 += __shfl_xor_sync(0xFFFFFFFFu, s2, o);
    if ((t & 31) == 0) red2[t >> 5] = s2;
    __syncthreads();
    float tot2 = 0.f;
#pragma unroll
    for (int i = 0; i < 8; i++) tot2 += red2[i];
    const float inv = rsqrtf(tot2 * (1.0f / Dv) + 1e-5f);

    const int c = t * 4;
    const float4 gm = *(const float4*)(gamma + c);
    const float4 bt = *(const float4*)(beta + c);
    float4 o;
    o.x = dx * inv * gm.x + bt.x;
    o.y = dy * inv * gm.y + bt.y;
    o.z = dz * inv * gm.z + bt.z;
    o.w = dw * inv * gm.w + bt.w;
    *(float4*)(out + (size_t)row * Dv + c) = o;
}

// ---------------------------------------------------------------------------
extern "C" void kernel_launch(void* const* d_in, const int* in_sizes, int n_in,
                              void* d_out, int out_size) {
    const float* hidden     = (const float*)d_in[0];
    const int*   dom        = (const int*)d_in[1];
    const float* down_W     = (const float*)d_in[2];
    const float* down_b     = (const float*)d_in[3];
    const float* up_W       = (const float*)d_in[4];
    const float* up_b       = (const float*)d_in[5];
    const float* expert_W   = (const float*)d_in[6];
    const float* expert_b   = (const float*)d_in[7];
    const float* domain_emb = (const float*)d_in[8];
    const float* gamma      = (const float*)d_in[9];
    const float* beta       = (const float*)d_in[10];
    float* out = (float*)d_out;

    cudaFuncSetAttribute(hmma_gemm<1>, cudaFuncAttributeMaxDynamicSharedMemorySize, SMEM_BYTES);
    cudaFuncSetAttribute(hmma_gemm<2>, cudaFuncAttributeMaxDynamicSharedMemorySize, SMEM_BYTES);
    cudaFuncSetAttribute(hmma_gemm<3>, cudaFuncAttributeMaxDynamicSharedMemorySize, SMEM_BYTES);

    prep_ids<<<1, 1>>>(dom);

    // one-time weight conversions (fp16)
    __half *dwh, *uwh, *ewh;
    cudaGetSymbolAddress((void**)&dwh, g_dwh);
    cudaGetSymbolAddress((void**)&uwh, g_uwh);
    cudaGetSymbolAddress((void**)&ewh, g_ewh);
    conv_w<<<128, 512>>>(down_W, dwh, Av * Dv / 4);
    conv_w<<<128, 512>>>(up_W, uwh, Dv * Av / 4);
    conv_w<<<256, 512>>>(expert_W, ewh, Ev * Av * Av / 4);

    // Stage 1: down-proj + GELU   (M=32768, N=256,  K=1024)
    hmma_gemm<1><<<dim3(1, Mrows / 128), 512, SMEM_BYTES>>>(hidden, down_b, nullptr);
    // Stage 2: per-batch expert   (per batch M=1024, N=256, K=256)
    hmma_gemm<2><<<dim3(1, Sv / 128, Bv), 512, SMEM_BYTES>>>(nullptr, expert_b, domain_emb);
    // Stage 3: up-proj + residual (M=32768, N=1024, K=256)
    hmma_gemm<3><<<dim3(Dv / 256, Mrows / 128), 512, SMEM_BYTES>>>(nullptr, up_b, hidden);
    // Stage 4: LayerNorm
    ln_kernel<<<Mrows, 256>>>(gamma, beta, out);
}